// round 1
// baseline (speedup 1.0000x reference)
#include <cuda_runtime.h>
#include <cstddef>

// RNNModel: 2-layer tanh RNN (B=2048, T=512, I=8, H=64) + FC(64->1) on last step.
//
// Strategy: fp32 SIMT, f32x2 packed FMAs (fma.rn.f32x2), weights streamed from
// __constant__ memory (uniform port / LDCU), h state double-buffered in smem.
// Block = 32 batch x 64 h ; warp = 8 j-rows x 32 batch lanes. 64 blocks.

#define T_STEPS 512
#define HDIM    64
#define IDIM    8
#define BB      32   // batch per block
#define NJ      8    // j rows per warp

// Weights in constant memory, viewed as 16B vectors (2 packed f32 pairs each).
// Layouts are exactly the row-major source layouts (row j contiguous), so a
// straight byte copy works.
__constant__ ulonglong2 cW0[HDIM * 2];     // W_ih0 [64][8]  -> [j][2 quads]
__constant__ ulonglong2 cWhh0[HDIM * 16];  // W_hh0 [64][64] -> [j][16 quads]
__constant__ ulonglong2 cWih1[HDIM * 16];  // W_ih1 [64][64]
__constant__ ulonglong2 cWhh1[HDIM * 16];  // W_hh1 [64][64]

__device__ __forceinline__ void ffma2(unsigned long long& acc,
                                      unsigned long long a,
                                      unsigned long long b) {
    // packed (f32,f32) fma: acc = a*b + acc, elementwise on both halves
    asm("fma.rn.f32x2 %0, %1, %2, %0;" : "+l"(acc) : "l"(a), "l"(b));
}

__global__ void __launch_bounds__(256, 1)
rnn_fused_kernel(const float* __restrict__ x,
                 const float* __restrict__ bi0, const float* __restrict__ bh0,
                 const float* __restrict__ bi1, const float* __restrict__ bh1,
                 const float* __restrict__ fcw, const float* __restrict__ fcb,
                 float* __restrict__ out)
{
    // h state: [parity][quad(=4 h components)][batch lane], 16B elements.
    __shared__ ulonglong2 h0s[2][16][BB];   // 16 KB
    __shared__ ulonglong2 h1s[2][16][BB];   // 16 KB

    const int lane  = threadIdx.x & 31;
    const int w     = threadIdx.x >> 5;
    const int jbase = w * NJ;
    const int b     = blockIdx.x * BB + lane;

    // Zero the parity-1 buffers (read as "previous h" at t=0).
    {
        ulonglong2 z; z.x = 0ull; z.y = 0ull;
        ulonglong2* p0 = &h0s[1][0][0];
        ulonglong2* p1 = &h1s[1][0][0];
        for (int i = threadIdx.x; i < 16 * BB; i += 256) { p0[i] = z; p1[i] = z; }
    }

    // Fold biases once (uniform per warp).
    float bias0[NJ], bias1[NJ];
#pragma unroll
    for (int jj = 0; jj < NJ; jj++) {
        bias0[jj] = bi0[jbase + jj] + bh0[jbase + jj];
        bias1[jj] = bi1[jbase + jj] + bh1[jbase + jj];
    }
    __syncthreads();

    // x[b][t][0..7] = 2 ulonglong2 per step, per batch element.
    const ulonglong2* xp =
        reinterpret_cast<const ulonglong2*>(x) + (size_t)b * (T_STEPS * IDIM / 4);
    ulonglong2 xc0 = xp[0];
    ulonglong2 xc1 = xp[1];

    unsigned long long acc[NJ];

    for (int t = 0; t < T_STEPS; t++) {
        const int p  = t & 1;
        const int pp = p ^ 1;

        // Prefetch next step's x (hides DRAM latency behind this step's FMAs).
        const int tn = (t + 1 < T_STEPS) ? (t + 1) : t;
        const ulonglong2 xn0 = xp[2 * tn];
        const ulonglong2 xn1 = xp[2 * tn + 1];

        // ---------------- layer 0 ----------------
        // acc = bias (low half) ; high half starts at +0.0f
#pragma unroll
        for (int jj = 0; jj < NJ; jj++) {
            acc[jj] = (unsigned long long)__float_as_uint(bias0[jj]);
            const ulonglong2 w0 = cW0[(jbase + jj) * 2 + 0];
            const ulonglong2 w1 = cW0[(jbase + jj) * 2 + 1];
            ffma2(acc[jj], w0.x, xc0.x);
            ffma2(acc[jj], w0.y, xc0.y);
            ffma2(acc[jj], w1.x, xc1.x);
            ffma2(acc[jj], w1.y, xc1.y);
        }
#pragma unroll 4
        for (int q = 0; q < 16; q++) {
            const ulonglong2 hv = h0s[pp][q][lane];
#pragma unroll
            for (int jj = 0; jj < NJ; jj++) {
                const ulonglong2 wv = cWhh0[(jbase + jj) * 16 + q];
                ffma2(acc[jj], wv.x, hv.x);
                ffma2(acc[jj], wv.y, hv.y);
            }
        }
#pragma unroll
        for (int jj = 0; jj < NJ; jj++) {
            const float lo = __uint_as_float((unsigned int)acc[jj]);
            const float hi = __uint_as_float((unsigned int)(acc[jj] >> 32));
            const float hval = tanhf(lo + hi);
            const int j = jbase + jj;
            reinterpret_cast<float*>(&h0s[p][j >> 2][lane])[j & 3] = hval;
        }
        __syncthreads();   // the single per-step barrier

        // ---------------- layer 1 ----------------
#pragma unroll
        for (int jj = 0; jj < NJ; jj++)
            acc[jj] = (unsigned long long)__float_as_uint(bias1[jj]);

#pragma unroll 4
        for (int q = 0; q < 16; q++) {
            const ulonglong2 hv = h0s[p][q][lane];
#pragma unroll
            for (int jj = 0; jj < NJ; jj++) {
                const ulonglong2 wv = cWih1[(jbase + jj) * 16 + q];
                ffma2(acc[jj], wv.x, hv.x);
                ffma2(acc[jj], wv.y, hv.y);
            }
        }
#pragma unroll 4
        for (int q = 0; q < 16; q++) {
            const ulonglong2 hv = h1s[pp][q][lane];
#pragma unroll
            for (int jj = 0; jj < NJ; jj++) {
                const ulonglong2 wv = cWhh1[(jbase + jj) * 16 + q];
                ffma2(acc[jj], wv.x, hv.x);
                ffma2(acc[jj], wv.y, hv.y);
            }
        }
#pragma unroll
        for (int jj = 0; jj < NJ; jj++) {
            const float lo = __uint_as_float((unsigned int)acc[jj]);
            const float hi = __uint_as_float((unsigned int)(acc[jj] >> 32));
            const float hval = tanhf(lo + hi);
            const int j = jbase + jj;
            reinterpret_cast<float*>(&h1s[p][j >> 2][lane])[j & 3] = hval;
        }

        xc0 = xn0;
        xc1 = xn1;
        // No trailing barrier needed: the next step's mid barrier orders
        // this step's h1 writes against the next step's h1 reads, and layer 0
        // only touches buffers already ordered by this step's barrier.
    }

    __syncthreads();

    // FC epilogue: out[b] = sum_j h1_final[j] * fcw[j] + fcb[0].
    // Final parity: (T_STEPS-1)&1 = 1.
    if (w == 0) {
        float sum = fcb[0];
#pragma unroll 4
        for (int q = 0; q < 16; q++) {
            const float4 hv = *reinterpret_cast<const float4*>(&h1s[1][q][lane]);
            const float4 wv = *reinterpret_cast<const float4*>(fcw + q * 4);
            sum += hv.x * wv.x + hv.y * wv.y + hv.z * wv.z + hv.w * wv.w;
        }
        out[b] = sum;
    }
}

extern "C" void kernel_launch(void* const* d_in, const int* in_sizes, int n_in,
                              void* d_out, int out_size)
{
    // Input order (setup_inputs): x, W_ih0, W_hh0, b_ih0, b_hh0,
    //                             W_ih1, W_hh1, b_ih1, b_hh1, fc_w, fc_b
    (void)in_sizes; (void)n_in; (void)out_size;

    // Stage weights into constant memory (D2D async memcpys: graph-capturable).
    cudaMemcpyToSymbolAsync(cW0,   d_in[1], HDIM * IDIM * sizeof(float), 0,
                            cudaMemcpyDeviceToDevice, 0);
    cudaMemcpyToSymbolAsync(cWhh0, d_in[2], HDIM * HDIM * sizeof(float), 0,
                            cudaMemcpyDeviceToDevice, 0);
    cudaMemcpyToSymbolAsync(cWih1, d_in[5], HDIM * HDIM * sizeof(float), 0,
                            cudaMemcpyDeviceToDevice, 0);
    cudaMemcpyToSymbolAsync(cWhh1, d_in[6], HDIM * HDIM * sizeof(float), 0,
                            cudaMemcpyDeviceToDevice, 0);

    rnn_fused_kernel<<<64, 256>>>(
        (const float*)d_in[0],
        (const float*)d_in[3], (const float*)d_in[4],
        (const float*)d_in[7], (const float*)d_in[8],
        (const float*)d_in[9], (const float*)d_in[10],
        (float*)d_out);
}

// round 3
// speedup vs baseline: 20.6161x; 20.6161x over previous
#include <cuda_runtime.h>
#include <cstddef>

// RNNModel: 2-layer tanh RNN (B=2048, T=512, I=8, H=64) + FC(64->1) on last step.
//
// R2 design: weights live in SHARED memory (constant cache thrashed in R1).
// 128 blocks x 256 threads; block = 16 batches x 64 h-rows.
// Warp = 16 batch lanes x 2 j-half groups; each thread owns 4 j rows = 1 h quad.
// fp32 f32x2 packed FMAs; weight rows for the two j-halves interleaved 16B apart
// so every weight LDS.128 touches 32 contiguous bytes (conflict-free broadcast).

#define T_STEPS 512
#define HDIM    64
#define IDIM    8
#define BB      16    // batch per block
#define NJ      4     // j rows per thread

// float4 counts in dynamic smem
#define OFF_WHH0 0
#define OFF_WIH1 1024
#define OFF_WHH1 2048
#define OFF_WIH0 3072           // 2*64
#define OFF_H0   3200           // [2][16][16]
#define OFF_H1   3712
#define SMEM_F4  4224
#define SMEM_BYTES (SMEM_F4 * 16)

__device__ __forceinline__ void ffma2(unsigned long long& acc,
                                      unsigned long long a,
                                      unsigned long long b) {
    asm("fma.rn.f32x2 %0, %1, %2, %0;" : "+l"(acc) : "l"(a), "l"(b));
}

__device__ __forceinline__ float fast_tanh(float x) {
    const float ax = fabsf(x);
    const float e  = __expf(-2.0f * ax);
    const float r  = __fdividef(1.0f - e, 1.0f + e);
    return copysignf(r, x);
}

// reorder row j so the two j-half rows used by one warp sit 16B apart
__device__ __forceinline__ int row_pos(int j) {
    const int r = j & 7;
    return (j & 0x38) | ((r & 3) << 1) | (r >> 2);
}

__global__ void __launch_bounds__(256, 1)
rnn_fused_kernel(const float* __restrict__ x,
                 const float* __restrict__ Wih0, const float* __restrict__ Whh0,
                 const float* __restrict__ bi0,  const float* __restrict__ bh0,
                 const float* __restrict__ Wih1, const float* __restrict__ Whh1,
                 const float* __restrict__ bi1,  const float* __restrict__ bh1,
                 const float* __restrict__ fcw,  const float* __restrict__ fcb,
                 float* __restrict__ out)
{
    extern __shared__ float4 smem[];
    ulonglong2* sWhh0 = reinterpret_cast<ulonglong2*>(smem + OFF_WHH0);
    ulonglong2* sWih1 = reinterpret_cast<ulonglong2*>(smem + OFF_WIH1);
    ulonglong2* sWhh1 = reinterpret_cast<ulonglong2*>(smem + OFF_WHH1);
    ulonglong2* sWih0 = reinterpret_cast<ulonglong2*>(smem + OFF_WIH0);
    ulonglong2* h0v   = reinterpret_cast<ulonglong2*>(smem + OFF_H0);
    ulonglong2* h1v   = reinterpret_cast<ulonglong2*>(smem + OFF_H1);

    const int tid   = threadIdx.x;
    const int lane  = tid & 31;
    const int w     = tid >> 5;
    const int jhalf = lane >> 4;       // 0/1
    const int bl    = lane & 15;       // batch within block
    const int b     = blockIdx.x * BB + bl;
    const int myquad = w * 2 + jhalf;  // this thread's h quad (j = 4*myquad..+3)

    // ---- fill weight smem (reordered), zero h parity-1 buffers ----
    {
        float* fWhh0 = reinterpret_cast<float*>(sWhh0);
        float* fWih1 = reinterpret_cast<float*>(sWih1);
        float* fWhh1 = reinterpret_cast<float*>(sWhh1);
        float* fWih0 = reinterpret_cast<float*>(sWih0);
        for (int idx = tid; idx < HDIM * HDIM; idx += 256) {
            const int j = idx >> 6, k = idx & 63;
            const int f = ((k >> 2) * 64 + row_pos(j)) * 4 + (k & 3);
            fWhh0[f] = Whh0[idx];
            fWih1[f] = Wih1[idx];
            fWhh1[f] = Whh1[idx];
        }
        for (int idx = tid; idx < HDIM * IDIM; idx += 256) {
            const int j = idx >> 3, k = idx & 7;
            fWih0[((k >> 2) * 64 + row_pos(j)) * 4 + (k & 3)] = Wih0[idx];
        }
        ulonglong2 z; z.x = 0ull; z.y = 0ull;
        for (int i = tid; i < 16 * BB; i += 256) {
            h0v[(1 * 16) * BB + i] = z;     // parity 1
            h1v[(1 * 16) * BB + i] = z;
        }
    }

    // fold biases for this thread's 4 rows: j = myquad*4 + jj
    float bias0[NJ], bias1[NJ];
#pragma unroll
    for (int jj = 0; jj < NJ; jj++) {
        const int j = myquad * 4 + jj;
        bias0[jj] = bi0[j] + bh0[j];
        bias1[jj] = bi1[j] + bh1[j];
    }
    __syncthreads();

    // weight smem index base for this thread (per q): q*64 + w*8 + jj*2 + jhalf
    const int wb = w * 8 + jhalf;

    // x[b][t][0..7] = 2 ulonglong2 per step
    const ulonglong2* xp =
        reinterpret_cast<const ulonglong2*>(x) + (size_t)b * (T_STEPS * IDIM / 4);
    ulonglong2 xc0 = xp[0];
    ulonglong2 xc1 = xp[1];

    unsigned long long acc[NJ];

    for (int t = 0; t < T_STEPS; t++) {
        const int p  = t & 1;
        const int pp = p ^ 1;

        const int tn = (t + 1 < T_STEPS) ? (t + 1) : t;
        const ulonglong2 xn0 = xp[2 * tn];
        const ulonglong2 xn1 = xp[2 * tn + 1];

        // ---------------- layer 0 ----------------
#pragma unroll
        for (int jj = 0; jj < NJ; jj++) {
            acc[jj] = (unsigned long long)__float_as_uint(bias0[jj]);
            const ulonglong2 w0 = sWih0[0 * 64 + wb + jj * 2];
            const ulonglong2 w1 = sWih0[1 * 64 + wb + jj * 2];
            ffma2(acc[jj], w0.x, xc0.x);
            ffma2(acc[jj], w0.y, xc0.y);
            ffma2(acc[jj], w1.x, xc1.x);
            ffma2(acc[jj], w1.y, xc1.y);
        }
#pragma unroll 4
        for (int q = 0; q < 16; q++) {
            const ulonglong2 hv = h0v[(pp * 16 + q) * BB + bl];
#pragma unroll
            for (int jj = 0; jj < NJ; jj++) {
                const ulonglong2 wv = sWhh0[q * 64 + wb + jj * 2];
                ffma2(acc[jj], wv.x, hv.x);
                ffma2(acc[jj], wv.y, hv.y);
            }
        }
        {
            float4 hq;
            float* hp = &hq.x;
#pragma unroll
            for (int jj = 0; jj < NJ; jj++) {
                const float lo = __uint_as_float((unsigned int)acc[jj]);
                const float hi = __uint_as_float((unsigned int)(acc[jj] >> 32));
                hp[jj] = fast_tanh(lo + hi);
            }
            reinterpret_cast<float4*>(h0v)[(p * 16 + myquad) * BB + bl] = hq;
        }
        __syncthreads();   // single per-step barrier

        // ---------------- layer 1 ----------------
#pragma unroll
        for (int jj = 0; jj < NJ; jj++)
            acc[jj] = (unsigned long long)__float_as_uint(bias1[jj]);

#pragma unroll 4
        for (int q = 0; q < 16; q++) {
            const ulonglong2 hv = h0v[(p * 16 + q) * BB + bl];
#pragma unroll
            for (int jj = 0; jj < NJ; jj++) {
                const ulonglong2 wv = sWih1[q * 64 + wb + jj * 2];
                ffma2(acc[jj], wv.x, hv.x);
                ffma2(acc[jj], wv.y, hv.y);
            }
        }
#pragma unroll 4
        for (int q = 0; q < 16; q++) {
            const ulonglong2 hv = h1v[(pp * 16 + q) * BB + bl];
#pragma unroll
            for (int jj = 0; jj < NJ; jj++) {
                const ulonglong2 wv = sWhh1[q * 64 + wb + jj * 2];
                ffma2(acc[jj], wv.x, hv.x);
                ffma2(acc[jj], wv.y, hv.y);
            }
        }
        {
            float4 hq;
            float* hp = &hq.x;
#pragma unroll
            for (int jj = 0; jj < NJ; jj++) {
                const float lo = __uint_as_float((unsigned int)acc[jj]);
                const float hi = __uint_as_float((unsigned int)(acc[jj] >> 32));
                hp[jj] = fast_tanh(lo + hi);
            }
            reinterpret_cast<float4*>(h1v)[(p * 16 + myquad) * BB + bl] = hq;
        }

        xc0 = xn0;
        xc1 = xn1;
        // next step's mid barrier orders this step's h1 writes vs next reads
    }

    __syncthreads();

    // FC epilogue: out[b] = sum_j h1_final[j] * fcw[j] + fcb[0]; final parity = 1.
    if (w == 0 && jhalf == 0) {
        float sum = fcb[0];
#pragma unroll 4
        for (int q = 0; q < 16; q++) {
            const float4 hv = reinterpret_cast<const float4*>(h1v)[(1 * 16 + q) * BB + bl];
            const float4 wv = *reinterpret_cast<const float4*>(fcw + q * 4);
            sum += hv.x * wv.x + hv.y * wv.y + hv.z * wv.z + hv.w * wv.w;
        }
        out[b] = sum;
    }
}

extern "C" void kernel_launch(void* const* d_in, const int* in_sizes, int n_in,
                              void* d_out, int out_size)
{
    // Input order: x, W_ih0, W_hh0, b_ih0, b_hh0, W_ih1, W_hh1, b_ih1, b_hh1, fc_w, fc_b
    (void)in_sizes; (void)n_in; (void)out_size;

    static bool attr_done = false;   // idempotent, deterministic (same every call)
    if (!attr_done) {
        cudaFuncSetAttribute(rnn_fused_kernel,
                             cudaFuncAttributeMaxDynamicSharedMemorySize, SMEM_BYTES);
        attr_done = true;
    }

    rnn_fused_kernel<<<128, 256, SMEM_BYTES>>>(
        (const float*)d_in[0],
        (const float*)d_in[1], (const float*)d_in[2],
        (const float*)d_in[3], (const float*)d_in[4],
        (const float*)d_in[5], (const float*)d_in[6],
        (const float*)d_in[7], (const float*)d_in[8],
        (const float*)d_in[9], (const float*)d_in[10],
        (float*)d_out);
}

// round 4
// speedup vs baseline: 20.6405x; 1.0012x over previous
#include <cuda_runtime.h>
#include <cstddef>

// RNNModel: 2-layer tanh RNN (B=2048, T=512, I=8, H=64) + FC(64->1) on last step.
//
// R2 design: weights live in SHARED memory (constant cache thrashed in R1).
// 128 blocks x 256 threads; block = 16 batches x 64 h-rows.
// Warp = 16 batch lanes x 2 j-half groups; each thread owns 4 j rows = 1 h quad.
// fp32 f32x2 packed FMAs; weight rows for the two j-halves interleaved 16B apart
// so every weight LDS.128 touches 32 contiguous bytes (conflict-free broadcast).

#define T_STEPS 512
#define HDIM    64
#define IDIM    8
#define BB      16    // batch per block
#define NJ      4     // j rows per thread

// float4 counts in dynamic smem
#define OFF_WHH0 0
#define OFF_WIH1 1024
#define OFF_WHH1 2048
#define OFF_WIH0 3072           // 2*64
#define OFF_H0   3200           // [2][16][16]
#define OFF_H1   3712
#define SMEM_F4  4224
#define SMEM_BYTES (SMEM_F4 * 16)

__device__ __forceinline__ void ffma2(unsigned long long& acc,
                                      unsigned long long a,
                                      unsigned long long b) {
    asm("fma.rn.f32x2 %0, %1, %2, %0;" : "+l"(acc) : "l"(a), "l"(b));
}

__device__ __forceinline__ float fast_tanh(float x) {
    const float ax = fabsf(x);
    const float e  = __expf(-2.0f * ax);
    const float r  = __fdividef(1.0f - e, 1.0f + e);
    return copysignf(r, x);
}

// reorder row j so the two j-half rows used by one warp sit 16B apart
__device__ __forceinline__ int row_pos(int j) {
    const int r = j & 7;
    return (j & 0x38) | ((r & 3) << 1) | (r >> 2);
}

__global__ void __launch_bounds__(256, 1)
rnn_fused_kernel(const float* __restrict__ x,
                 const float* __restrict__ Wih0, const float* __restrict__ Whh0,
                 const float* __restrict__ bi0,  const float* __restrict__ bh0,
                 const float* __restrict__ Wih1, const float* __restrict__ Whh1,
                 const float* __restrict__ bi1,  const float* __restrict__ bh1,
                 const float* __restrict__ fcw,  const float* __restrict__ fcb,
                 float* __restrict__ out)
{
    extern __shared__ float4 smem[];
    ulonglong2* sWhh0 = reinterpret_cast<ulonglong2*>(smem + OFF_WHH0);
    ulonglong2* sWih1 = reinterpret_cast<ulonglong2*>(smem + OFF_WIH1);
    ulonglong2* sWhh1 = reinterpret_cast<ulonglong2*>(smem + OFF_WHH1);
    ulonglong2* sWih0 = reinterpret_cast<ulonglong2*>(smem + OFF_WIH0);
    ulonglong2* h0v   = reinterpret_cast<ulonglong2*>(smem + OFF_H0);
    ulonglong2* h1v   = reinterpret_cast<ulonglong2*>(smem + OFF_H1);

    const int tid   = threadIdx.x;
    const int lane  = tid & 31;
    const int w     = tid >> 5;
    const int jhalf = lane >> 4;       // 0/1
    const int bl    = lane & 15;       // batch within block
    const int b     = blockIdx.x * BB + bl;
    const int myquad = w * 2 + jhalf;  // this thread's h quad (j = 4*myquad..+3)

    // ---- fill weight smem (reordered), zero h parity-1 buffers ----
    {
        float* fWhh0 = reinterpret_cast<float*>(sWhh0);
        float* fWih1 = reinterpret_cast<float*>(sWih1);
        float* fWhh1 = reinterpret_cast<float*>(sWhh1);
        float* fWih0 = reinterpret_cast<float*>(sWih0);
        for (int idx = tid; idx < HDIM * HDIM; idx += 256) {
            const int j = idx >> 6, k = idx & 63;
            const int f = ((k >> 2) * 64 + row_pos(j)) * 4 + (k & 3);
            fWhh0[f] = Whh0[idx];
            fWih1[f] = Wih1[idx];
            fWhh1[f] = Whh1[idx];
        }
        for (int idx = tid; idx < HDIM * IDIM; idx += 256) {
            const int j = idx >> 3, k = idx & 7;
            fWih0[((k >> 2) * 64 + row_pos(j)) * 4 + (k & 3)] = Wih0[idx];
        }
        ulonglong2 z; z.x = 0ull; z.y = 0ull;
        for (int i = tid; i < 16 * BB; i += 256) {
            h0v[(1 * 16) * BB + i] = z;     // parity 1
            h1v[(1 * 16) * BB + i] = z;
        }
    }

    // fold biases for this thread's 4 rows: j = myquad*4 + jj
    float bias0[NJ], bias1[NJ];
#pragma unroll
    for (int jj = 0; jj < NJ; jj++) {
        const int j = myquad * 4 + jj;
        bias0[jj] = bi0[j] + bh0[j];
        bias1[jj] = bi1[j] + bh1[j];
    }
    __syncthreads();

    // weight smem index base for this thread (per q): q*64 + w*8 + jj*2 + jhalf
    const int wb = w * 8 + jhalf;

    // x[b][t][0..7] = 2 ulonglong2 per step
    const ulonglong2* xp =
        reinterpret_cast<const ulonglong2*>(x) + (size_t)b * (T_STEPS * IDIM / 4);
    ulonglong2 xc0 = xp[0];
    ulonglong2 xc1 = xp[1];

    unsigned long long acc[NJ];

    for (int t = 0; t < T_STEPS; t++) {
        const int p  = t & 1;
        const int pp = p ^ 1;

        const int tn = (t + 1 < T_STEPS) ? (t + 1) : t;
        const ulonglong2 xn0 = xp[2 * tn];
        const ulonglong2 xn1 = xp[2 * tn + 1];

        // ---------------- layer 0 ----------------
#pragma unroll
        for (int jj = 0; jj < NJ; jj++) {
            acc[jj] = (unsigned long long)__float_as_uint(bias0[jj]);
            const ulonglong2 w0 = sWih0[0 * 64 + wb + jj * 2];
            const ulonglong2 w1 = sWih0[1 * 64 + wb + jj * 2];
            ffma2(acc[jj], w0.x, xc0.x);
            ffma2(acc[jj], w0.y, xc0.y);
            ffma2(acc[jj], w1.x, xc1.x);
            ffma2(acc[jj], w1.y, xc1.y);
        }
#pragma unroll 4
        for (int q = 0; q < 16; q++) {
            const ulonglong2 hv = h0v[(pp * 16 + q) * BB + bl];
#pragma unroll
            for (int jj = 0; jj < NJ; jj++) {
                const ulonglong2 wv = sWhh0[q * 64 + wb + jj * 2];
                ffma2(acc[jj], wv.x, hv.x);
                ffma2(acc[jj], wv.y, hv.y);
            }
        }
        {
            float4 hq;
            float* hp = &hq.x;
#pragma unroll
            for (int jj = 0; jj < NJ; jj++) {
                const float lo = __uint_as_float((unsigned int)acc[jj]);
                const float hi = __uint_as_float((unsigned int)(acc[jj] >> 32));
                hp[jj] = fast_tanh(lo + hi);
            }
            reinterpret_cast<float4*>(h0v)[(p * 16 + myquad) * BB + bl] = hq;
        }
        __syncthreads();   // single per-step barrier

        // ---------------- layer 1 ----------------
#pragma unroll
        for (int jj = 0; jj < NJ; jj++)
            acc[jj] = (unsigned long long)__float_as_uint(bias1[jj]);

#pragma unroll 4
        for (int q = 0; q < 16; q++) {
            const ulonglong2 hv = h0v[(p * 16 + q) * BB + bl];
#pragma unroll
            for (int jj = 0; jj < NJ; jj++) {
                const ulonglong2 wv = sWih1[q * 64 + wb + jj * 2];
                ffma2(acc[jj], wv.x, hv.x);
                ffma2(acc[jj], wv.y, hv.y);
            }
        }
#pragma unroll 4
        for (int q = 0; q < 16; q++) {
            const ulonglong2 hv = h1v[(pp * 16 + q) * BB + bl];
#pragma unroll
            for (int jj = 0; jj < NJ; jj++) {
                const ulonglong2 wv = sWhh1[q * 64 + wb + jj * 2];
                ffma2(acc[jj], wv.x, hv.x);
                ffma2(acc[jj], wv.y, hv.y);
            }
        }
        {
            float4 hq;
            float* hp = &hq.x;
#pragma unroll
            for (int jj = 0; jj < NJ; jj++) {
                const float lo = __uint_as_float((unsigned int)acc[jj]);
                const float hi = __uint_as_float((unsigned int)(acc[jj] >> 32));
                hp[jj] = fast_tanh(lo + hi);
            }
            reinterpret_cast<float4*>(h1v)[(p * 16 + myquad) * BB + bl] = hq;
        }

        xc0 = xn0;
        xc1 = xn1;
        // next step's mid barrier orders this step's h1 writes vs next reads
    }

    __syncthreads();

    // FC epilogue: out[b] = sum_j h1_final[j] * fcw[j] + fcb[0]; final parity = 1.
    if (w == 0 && jhalf == 0) {
        float sum = fcb[0];
#pragma unroll 4
        for (int q = 0; q < 16; q++) {
            const float4 hv = reinterpret_cast<const float4*>(h1v)[(1 * 16 + q) * BB + bl];
            const float4 wv = *reinterpret_cast<const float4*>(fcw + q * 4);
            sum += hv.x * wv.x + hv.y * wv.y + hv.z * wv.z + hv.w * wv.w;
        }
        out[b] = sum;
    }
}

extern "C" void kernel_launch(void* const* d_in, const int* in_sizes, int n_in,
                              void* d_out, int out_size)
{
    // Input order: x, W_ih0, W_hh0, b_ih0, b_hh0, W_ih1, W_hh1, b_ih1, b_hh1, fc_w, fc_b
    (void)in_sizes; (void)n_in; (void)out_size;

    static bool attr_done = false;   // idempotent, deterministic (same every call)
    if (!attr_done) {
        cudaFuncSetAttribute(rnn_fused_kernel,
                             cudaFuncAttributeMaxDynamicSharedMemorySize, SMEM_BYTES);
        attr_done = true;
    }

    rnn_fused_kernel<<<128, 256, SMEM_BYTES>>>(
        (const float*)d_in[0],
        (const float*)d_in[1], (const float*)d_in[2],
        (const float*)d_in[3], (const float*)d_in[4],
        (const float*)d_in[5], (const float*)d_in[6],
        (const float*)d_in[7], (const float*)d_in[8],
        (const float*)d_in[9], (const float*)d_in[10],
        (float*)d_out);
}